// round 13
// baseline (speedup 1.0000x reference)
#include <cuda_runtime.h>
#include <cuda_bf16.h>
#include <cuda_fp16.h>
#include <math.h>

#define Bq 2
#define Tq 2048
#define Cq 1024
#define Hq 16
#define Dq 64
#define Mq (Bq*Tq)          // 4096
#define EPSq 1e-6f
#define CHUNK 16
#define NCH (Tq/CHUNK)      // 128
#define VSEG 8              // v-rows per scan warp
#define NSEG (Dq/VSEG)      // 8 -> 256 blocks

typedef unsigned long long ull;
typedef unsigned int u32;

// ---------------- packed f32x2 helpers ---------------------------------------
__device__ __forceinline__ ull ffma2(ull a, ull b, ull c) {
    ull d; asm("fma.rn.f32x2 %0, %1, %2, %3;" : "=l"(d) : "l"(a), "l"(b), "l"(c)); return d;
}
__device__ __forceinline__ ull fmul2(ull a, ull b) {
    ull d; asm("mul.rn.f32x2 %0, %1, %2;" : "=l"(d) : "l"(a), "l"(b)); return d;
}
__device__ __forceinline__ ull fadd2(ull a, ull b) {
    ull d; asm("add.rn.f32x2 %0, %1, %2;" : "=l"(d) : "l"(a), "l"(b)); return d;
}
__device__ __forceinline__ ull pack2(float x, float y) {
    ull d; asm("mov.b64 %0, {%1, %2};" : "=l"(d) : "f"(x), "f"(y)); return d;
}
__device__ __forceinline__ float2 unpack2(ull v) {
    float x, y; asm("mov.b64 {%0, %1}, %2;" : "=f"(x), "=f"(y) : "l"(v));
    return make_float2(x, y);
}
__device__ __forceinline__ void cpa16(void* s, const void* g) {
    asm volatile("cp.async.cg.shared.global [%0], [%1], 16;"
        :: "r"((unsigned)__cvta_generic_to_shared(s)), "l"(g));
}
#define CP_COMMIT() asm volatile("cp.async.commit_group;")
#define CP_WAIT1()  asm volatile("cp.async.wait_group 1;")

// ---------------- mma.sync helpers (fp16, f32 accum) --------------------------
__device__ __forceinline__ void ldsm4(u32* r, u32 addr) {
    asm volatile("ldmatrix.sync.aligned.m8n8.x4.shared.b16 {%0,%1,%2,%3}, [%4];"
        : "=r"(r[0]), "=r"(r[1]), "=r"(r[2]), "=r"(r[3]) : "r"(addr));
}
__device__ __forceinline__ void mma16816h(float* d, const u32* a, u32 b0, u32 b1) {
    asm volatile("mma.sync.aligned.m16n8k16.row.col.f32.f16.f16.f32 "
        "{%0,%1,%2,%3}, {%4,%5,%6,%7}, {%8,%9}, {%0,%1,%2,%3};"
        : "+f"(d[0]), "+f"(d[1]), "+f"(d[2]), "+f"(d[3])
        : "r"(a[0]), "r"(a[1]), "r"(a[2]), "r"(a[3]), "r"(b0), "r"(b1));
}

// ---------------- scratch ----------------------------------------------------
__device__ float g_qpre[(size_t)Mq*Cq];
__device__ float g_kpre[(size_t)Mq*Cq];
__device__ float g_vpre[(size_t)Mq*Cq];
__device__ float g_gate[(size_t)Mq*Cq];
__device__ float g_q[(size_t)Mq*Cq];
__device__ float g_k[(size_t)Mq*Cq];
__device__ float g_v[(size_t)Mq*Cq];
__device__ float g_alT[(size_t)Mq*Hq];
__device__ float g_beT[(size_t)Mq*Hq];
__device__ float g_cos[(size_t)Tq*32];
__device__ float g_sin[(size_t)Tq*32];
__device__ __half g_xh[(size_t)Mq*Cq];
__device__ __half g_wh[(size_t)5*Cq*Cq];
__device__ __half g_ogh[(size_t)Mq*Cq];

// ---------------- fp16 pack helpers ------------------------------------------
__device__ __forceinline__ u32 packh(__half a, __half b) {
    return (u32)__half_as_ushort(a) | ((u32)__half_as_ushort(b) << 16);
}

// ---------------- merged prep: bg + rope table + x->fp16 + weights->fp16 -----
#define BGM 8
#define NB_BG (Mq/BGM)                   // 512
#define NB_ROPE 256
#define NB_SPLITH (Mq*Cq/4/256)          // 4096
#define NB_WSPLIT (5*(Cq*Cq/4)/256)      // 5120
#define NB_PREP (NB_BG + NB_ROPE + NB_SPLITH + NB_WSPLIT)

__global__ __launch_bounds__(256) void prep_kernel(
    const float* __restrict__ x,
    const float* __restrict__ w0, const float* __restrict__ w1,
    const float* __restrict__ w2, const float* __restrict__ w3,
    const float* __restrict__ w4,
    const float* __restrict__ Wb, const float* __restrict__ bb,
    const float* __restrict__ Wgk, const float* __restrict__ bgk,
    const float* __restrict__ A_log, const float* __restrict__ dt_bias,
    float* __restrict__ beT, float* __restrict__ alT,
    float* __restrict__ ct, float* __restrict__ st,
    __half* __restrict__ xh, __half* __restrict__ whi)
{
    __shared__ __align__(16) float xs[BGM][Cq];
    int blk = blockIdx.x;

    if (blk < NB_BG) {
        const int m0 = blk * BGM;
        const int tid = threadIdx.x;
        for (int i = tid; i < BGM * Cq / 4; i += 256) {
            int r = i / (Cq / 4), cc = i % (Cq / 4);
            ((float4*)xs[r])[cc] = ((const float4*)(x + (size_t)(m0 + r) * Cq))[cc];
        }
        __syncthreads();

        const int warp = tid >> 5, lane = tid & 31;
#pragma unroll
        for (int nn = 0; nn < 4; nn++) {
            int n = warp * 4 + nn;
            const float* wr = (n < 16) ? (Wb + (size_t)n * Cq) : (Wgk + (size_t)(n - 16) * Cq);
            float wv[32];
#pragma unroll
            for (int j = 0; j < 32; j++) wv[j] = __ldg(wr + j * 32 + lane);
#pragma unroll
            for (int r = 0; r < BGM; r++) {
                float acc = 0.f;
#pragma unroll
                for (int j = 0; j < 32; j++) acc = fmaf(xs[r][j * 32 + lane], wv[j], acc);
#pragma unroll
                for (int s = 16; s > 0; s >>= 1) acc += __shfl_xor_sync(0xffffffffu, acc, s);
                if (lane == 0) {
                    int m = m0 + r;
                    int b = m >> 11, t = m & 2047;
                    if (n < 16) {
                        beT[((size_t)b * Hq + n) * Tq + t] = 1.f / (1.f + expf(-(acc + bb[n])));
                    } else {
                        int hh = n - 16;
                        float gv = acc + bgk[hh] + dt_bias[hh];
                        float sp = (gv > 20.f) ? gv : log1pf(expf(gv));
                        alT[((size_t)b * Hq + hh) * Tq + t] = expf(-expf(A_log[hh]) * sp);
                    }
                }
            }
        }
        return;
    }
    blk -= NB_BG;

    if (blk < NB_ROPE) {
        int idx = blk * 256 + threadIdx.x;
        int t = idx >> 5;
        int i = idx & 31;
        double ar = (double)i / 32.0;
        double scaled_base = 10000.0 * pow(32.0, 64.0 / 62.0);
        double inv_freq = pow(scaled_base, -ar);
        double wavelen = 2.0 * M_PI * pow(10000.0, ar);
        double mscale = (wavelen - 1.0) / 31.0;
        mscale = mscale < 0.0 ? 0.0 : (mscale > 1.0 ? 1.0 : mscale);
        double scale = 1.0 + 31.0 * mscale;
        float fr = (float)(((double)t / scale) * inv_freq);
        ct[idx] = cosf(fr);
        st[idx] = sinf(fr);
        return;
    }
    blk -= NB_ROPE;

    if (blk < NB_SPLITH) {
        int i = blk * 256 + threadIdx.x;
        float4 v = ((const float4*)x)[i];
        ((uint2*)xh)[i] = make_uint2(
            packh(__float2half(v.x), __float2half(v.y)),
            packh(__float2half(v.z), __float2half(v.w)));
        return;
    }
    blk -= NB_SPLITH;
    {
        const int R4 = (Cq * Cq) / 4;
        int i = blk * 256 + threadIdx.x;
        int r = i / R4;
        int li = i - r * R4;
        const float* src = (r == 0) ? w0 : (r == 1) ? w1 : (r == 2) ? w2
                          : (r == 3) ? w3 : w4;
        float4 v = ((const float4*)src)[li];
        ((uint2*)(whi + (size_t)r * Cq * Cq))[li] = make_uint2(
            packh(__float2half(v.x), __float2half(v.y)),
            packh(__float2half(v.z), __float2half(v.w)));
    }
}

// ---------------- tensor-core fp16 single-pass GEMM (NT), 2 CTAs/SM ----------
#define TILE_B 16384                  // 128 rows x 128 B
#define STG_B (2*TILE_B)              // Ah | Bh = 32KB per stage
#define NSTG 2
#define TG_SMEM (NSTG*STG_B)          // 64KB -> 2 CTAs per SM

__device__ __forceinline__ u32 swz_off(int row, int c) {
    return (u32)(row * 128 + (((u32)c ^ ((u32)row & 7) ^ (((u32)row >> 3) & 1)) << 4));
}

struct TG4Out { float *o0, *o1, *o2, *o3; };

__device__ __forceinline__ void tgemm_body(
    const __half* Ah, const __half* Bh,
    float* C, int K, int ldc, int m0, int n0, char* ts)
{
    const u32 sbase = (u32)__cvta_generic_to_shared(ts);
    const int tid = threadIdx.x;
    const int wid = tid >> 5;
    const int lane = tid & 31;
    const int warp_m = wid & 3;
    const int warp_n = wid >> 2;
    const int nchk = K / 64;

    const int lrow = tid >> 1;
    const int ch0 = (tid & 1) * 4;
    const char* gAh = (const char*)(Ah + (size_t)(m0 + lrow) * K) + ch0 * 16;
    const char* gBh = (const char*)(Bh + (size_t)(n0 + lrow) * K) + ch0 * 16;
    u32 soff[4];
#pragma unroll
    for (int i = 0; i < 4; i++) soff[i] = swz_off(lrow, ch0 + i);

    auto load_chunk = [&](int c, int stg) {
        const size_t go = (size_t)c * 128;
        char* base = ts + stg * STG_B;
#pragma unroll
        for (int i = 0; i < 4; i++) {
            cpa16(base + soff[i],          gAh + go + i * 16);
            cpa16(base + TILE_B + soff[i], gBh + go + i * 16);
        }
    };

    const int lq = lane >> 3;
    const int lr = lane & 7;
    const int rowA0 = warp_m * 32 + lr + (lq & 1) * 8;
    const int rowB0 = warp_n * 64 + lr + (lq & 1) * 8;
    const int cq = lq >> 1;

    float acc[2][8][4];
#pragma unroll
    for (int i = 0; i < 2; i++)
#pragma unroll
        for (int j = 0; j < 8; j++)
#pragma unroll
            for (int l = 0; l < 4; l++) acc[i][j][l] = 0.f;

    load_chunk(0, 0); CP_COMMIT();
    load_chunk(1, 1); CP_COMMIT();

    for (int c = 0; c < nchk; c++) {
        const int stg = c & 1;
        CP_WAIT1();
        __syncthreads();

        const u32 stb = sbase + stg * STG_B;
#pragma unroll
        for (int ks = 0; ks < 4; ks++) {
            const int cc = ks * 2 + cq;
            u32 ahf[2][4], bhf[4][4];
#pragma unroll
            for (int mt = 0; mt < 2; mt++)
                ldsm4(ahf[mt], stb + swz_off(rowA0 + mt * 16, cc));
#pragma unroll
            for (int ntp = 0; ntp < 4; ntp++)
                ldsm4(bhf[ntp], stb + TILE_B + swz_off(rowB0 + ntp * 16, cc));
#pragma unroll
            for (int mt = 0; mt < 2; mt++)
#pragma unroll
                for (int ntp = 0; ntp < 4; ntp++) {
                    mma16816h(acc[mt][ntp * 2],     ahf[mt], bhf[ntp][0], bhf[ntp][2]);
                    mma16816h(acc[mt][ntp * 2 + 1], ahf[mt], bhf[ntp][1], bhf[ntp][3]);
                }
        }

        __syncthreads();
        if (c + 2 < nchk) load_chunk(c + 2, stg);
        CP_COMMIT();
    }

    const int g = lane >> 2;
    const int tg = lane & 3;
#pragma unroll
    for (int mt = 0; mt < 2; mt++) {
        int mrow = m0 + warp_m * 32 + mt * 16 + g;
#pragma unroll
        for (int nt = 0; nt < 8; nt++) {
            int ncol = n0 + warp_n * 64 + nt * 8 + tg * 2;
            *(float2*)(C + (size_t)mrow * ldc + ncol) =
                make_float2(acc[mt][nt][0], acc[mt][nt][1]);
            *(float2*)(C + (size_t)(mrow + 8) * ldc + ncol) =
                make_float2(acc[mt][nt][2], acc[mt][nt][3]);
        }
    }
}

__global__ __launch_bounds__(256, 2) void tgemm_nt(
    const __half* __restrict__ Ah, const __half* __restrict__ Bh,
    float* __restrict__ C, int K, int ldc)
{
    extern __shared__ __align__(1024) char ts[];
    tgemm_body(Ah, Bh, C, K, ldc, blockIdx.x * 128, blockIdx.y * 128, ts);
}

__global__ __launch_bounds__(256, 2) void tgemm4_nt(
    const __half* __restrict__ Ah, const __half* __restrict__ Wh,
    TG4Out outs, int K, int ldc)
{
    extern __shared__ __align__(1024) char ts[];
    const int wsel = blockIdx.y >> 3;
    const int n0 = (blockIdx.y & 7) * 128;
    const size_t CC = (size_t)Cq * Cq;
    float* C = (wsel == 0) ? outs.o0 : (wsel == 1) ? outs.o1
             : (wsel == 2) ? outs.o2 : outs.o3;
    tgemm_body(Ah, Wh + wsel * CC, C, K, ldc, blockIdx.x * 128, n0, ts);
}

// ---------------- conv(K=4)+silu, RoPE + l2norm (4 t per block) --------------
__global__ __launch_bounds__(256) void conv_rope_kernel(
    const float* __restrict__ qpre, const float* __restrict__ kpre,
    const float* __restrict__ vpre,
    const float* __restrict__ cqw, const float* __restrict__ cqb,
    const float* __restrict__ ckw, const float* __restrict__ ckb,
    const float* __restrict__ cvw, const float* __restrict__ cvb,
    const float* __restrict__ ct, const float* __restrict__ st,
    float* __restrict__ qo, float* __restrict__ ko, float* __restrict__ vo)
{
    const int blk = blockIdx.x;
    const int b = blk / (Hq * (Tq / 4));
    const int rem = blk % (Hq * (Tq / 4));
    const int h = rem / (Tq / 4);
    const int t0 = (rem % (Tq / 4)) * 4;
    const int tid = threadIdx.x;

    __shared__ __align__(16) float spre[3][7][64];
    __shared__ float sq[4][64], sk[4][64];
    __shared__ float redq[4][2], redk[4][2];

    {
        const int NF4 = 3 * 7 * 16;
        for (int i = tid; i < NF4; i += 256) {
            int ten = i / 112;
            int r = (i % 112) / 16;
            int c4 = i % 16;
            int trow = t0 - 3 + r;
            float4 v = make_float4(0.f, 0.f, 0.f, 0.f);
            if (trow >= 0) {
                const float* src = (ten == 0) ? qpre : (ten == 1) ? kpre : vpre;
                v = ((const float4*)(src + ((size_t)b * Tq + trow) * Cq + h * 64))[c4];
            }
            ((float4*)&spre[ten][r][0])[c4] = v;
        }
    }
    __syncthreads();

    const int g = tid >> 6;
    const int d = tid & 63;
    const int t = t0 + g;
    const int c = h * Dq + d;
    const size_t gidx = ((size_t)b * Tq + t) * Cq + c;

    float aq = __ldg(cqb + c), ak = __ldg(ckb + c), av = __ldg(cvb + c);
#pragma unroll
    for (int i = 0; i < 4; i++) {
        float wq = __ldg(cqw + c * 4 + i);
        float wk = __ldg(ckw + c * 4 + i);
        float wv = __ldg(cvw + c * 4 + i);
        aq = fmaf(spre[0][g + i][d], wq, aq);
        ak = fmaf(spre[1][g + i][d], wk, ak);
        av = fmaf(spre[2][g + i][d], wv, av);
    }
    vo[gidx] = av / (1.f + expf(-av));
    sq[g][d] = aq / (1.f + expf(-aq));
    sk[g][d] = ak / (1.f + expf(-ak));
    __syncthreads();

    int j = d & 31;
    int ci = (2 * j) & 31;
    float ce = ct[(size_t)t * 32 + ci];
    float se = st[(size_t)t * 32 + ci];
    float q1 = sq[g][2 * j], q2 = sq[g][2 * j + 1];
    float k1 = sk[g][2 * j], k2 = sk[g][2 * j + 1];
    float rq = (d < 32) ? (q1 * ce - q2 * se) : (q1 * se + q2 * ce);
    float rk = (d < 32) ? (k1 * ce - k2 * se) : (k1 * se + k2 * ce);

    float sq2 = rq * rq, sk2 = rk * rk;
#pragma unroll
    for (int s = 16; s > 0; s >>= 1) {
        sq2 += __shfl_xor_sync(0xffffffffu, sq2, s);
        sk2 += __shfl_xor_sync(0xffffffffu, sk2, s);
    }
    int hw = (tid >> 5) & 1;
    if ((tid & 31) == 0) { redq[g][hw] = sq2; redk[g][hw] = sk2; }
    __syncthreads();
    float qn = redq[g][0] + redq[g][1];
    float kn = redk[g][0] + redk[g][1];
    float qinv = 1.f / fmaxf(sqrtf(qn), 1e-12f);
    float kinv = 1.f / fmaxf(sqrtf(kn), 1e-12f);
    qo[gidx] = rq * qinv;
    ko[gidx] = rk * kinv;
}

// ---------------- gated-delta scan: 2-step WY, streamed operands -------------
// warp per (b,h,vseg of 8 rows); lane = (vr = lane>>2, kg = lane&3, 16 cols).
// Per pair of steps: 4 concurrent matvecs vs old S (operands streamed from
// smem, not held), one concurrent shfl wave, scalar chain c1->p2->c2, 3-term
// S update with k1/k2 reloaded from smem. Cross dots precomputed per chunk.
__global__ __launch_bounds__(32, 8) void scan_kernel(
    const float* __restrict__ q, const float* __restrict__ k,
    const float* __restrict__ v,
    const float* __restrict__ alT, const float* __restrict__ beT,
    const float* __restrict__ Dp, float* __restrict__ valout)
{
    const int blk = blockIdx.x;
    const int bh = blk >> 3;
    const int seg = blk & 7;
    const int b = bh >> 4;
    const int h = bh & 15;
    const int lane = threadIdx.x;
    const int vr = lane >> 2;
    const int kg = lane & 3;

    __shared__ __align__(16) float sQ[2][CHUNK][64];
    __shared__ __align__(16) float sK[2][CHUNK][64];
    __shared__ __align__(16) float sV[2][CHUNK][VSEG];
    __shared__ __align__(16) float sA[2][CHUNK];
    __shared__ __align__(16) float sB[2][CHUNK];
    __shared__ float sD[2][32];

    const size_t base  = (size_t)b * Tq * Cq + h * Dq;
    const size_t vbase = base + seg * VSEG;
    const size_t abb   = (size_t)bh * Tq;

    auto load_chunk = [&](int c, int stg) {
        const size_t rowoff = (size_t)c * CHUNK * Cq;
#pragma unroll
        for (int it = 0; it < 8; it++) {
            int idx = it * 32 + lane;
            int row = idx >> 4;
            int col = (idx & 15) * 4;
            cpa16(&sQ[stg][row][col], q + base + rowoff + (size_t)row * Cq + col);
            cpa16(&sK[stg][row][col], k + base + rowoff + (size_t)row * Cq + col);
        }
        {
            int row = lane >> 1;
            int col = (lane & 1) * 4;
            cpa16(&sV[stg][row][col], v + vbase + rowoff + (size_t)row * Cq + col);
        }
        if (lane < 4)      cpa16(&sA[stg][lane * 4], alT + abb + c * CHUNK + lane * 4);
        else if (lane < 8) cpa16(&sB[stg][(lane - 4) * 4], beT + abb + c * CHUNK + (lane - 4) * 4);
    };

    ull S2[8];
#pragma unroll
    for (int j = 0; j < 8; j++) S2[j] = 0ULL;
    const float dp = Dp[h];

    load_chunk(0, 0); CP_COMMIT();
    load_chunk(1, 1); CP_COMMIT();
    CP_WAIT1();
    __syncwarp();

    for (int c = 0; c < NCH; c++) {
        const int stg = c & 1;

        // ---- per-chunk cross dots: lane -> (pair = lane>>2, which = lane&3)
        //  which 0: k1.k2   1: k1.q1   2: k1.q2   3: k2.q2
        {
            const int pi = lane >> 2, wh = lane & 3;
            const int s1 = pi * 2, s2 = s1 + 1;
            const ull* Aa = (const ull*)((wh == 3) ? &sK[stg][s2][0] : &sK[stg][s1][0]);
            const ull* Bb = (wh == 0) ? (const ull*)&sK[stg][s2][0]
                          : (wh == 1) ? (const ull*)&sQ[stg][s1][0]
                                      : (const ull*)&sQ[stg][s2][0];
            ull d0 = 0, d1 = 0, d2 = 0, d3 = 0;
#pragma unroll
            for (int j = 0; j < 8; j++) {
                d0 = ffma2(Aa[4 * j + 0], Bb[4 * j + 0], d0);
                d1 = ffma2(Aa[4 * j + 1], Bb[4 * j + 1], d1);
                d2 = ffma2(Aa[4 * j + 2], Bb[4 * j + 2], d2);
                d3 = ffma2(Aa[4 * j + 3], Bb[4 * j + 3], d3);
            }
            float2 u = unpack2(fadd2(fadd2(d0, d1), fadd2(d2, d3)));
            sD[stg][lane] = u.x + u.y;
        }
        __syncwarp();

#pragma unroll 2
        for (int pi = 0; pi < 8; pi++) {
            const int s1 = pi * 2, s2 = s1 + 1;
            const float a1v = sA[stg][s1], b1v = sB[stg][s1];
            const float a2v = sA[stg][s2], b2v = sB[stg][s2];
            const float vv1 = sV[stg][s1][vr], vv2 = sV[stg][s2][vr];
            const float kk   = sD[stg][pi * 4 + 0];
            const float kq11 = sD[stg][pi * 4 + 1];
            const float kq12 = sD[stg][pi * 4 + 2];
            const float kq22 = sD[stg][pi * 4 + 3];

            // 4 matvec partials vs old S, operands streamed from smem
            const ull* k1p = (const ull*)&sK[stg][s1][kg * 16];
            const ull* k2p = (const ull*)&sK[stg][s2][kg * 16];
            const ull* q1p = (const ull*)&sQ[stg][s1][kg * 16];
            const ull* q2p = (const ull*)&sQ[stg][s2][kg * 16];
            ull t1 = 0, t2 = 0, t3 = 0, t4 = 0;
            ull u1 = 0, u2 = 0, u3 = 0, u4 = 0;
#pragma unroll
            for (int j = 0; j < 4; j++) {
                t1 = ffma2(S2[j], k1p[j], t1);  u1 = ffma2(S2[j + 4], k1p[j + 4], u1);
                t2 = ffma2(S2[j], k2p[j], t2);  u2 = ffma2(S2[j + 4], k2p[j + 4], u2);
                t3 = ffma2(S2[j], q1p[j], t3);  u3 = ffma2(S2[j + 4], q1p[j + 4], u3);
                t4 = ffma2(S2[j], q2p[j], t4);  u4 = ffma2(S2[j + 4], q2p[j + 4], u4);
            }
            float2 w1 = unpack2(fadd2(t1, u1));
            float2 w2 = unpack2(fadd2(t2, u2));
            float2 w3 = unpack2(fadd2(t3, u3));
            float2 w4 = unpack2(fadd2(t4, u4));
            float Sk1 = w1.x + w1.y, Sk2 = w2.x + w2.y;
            float Sq1 = w3.x + w3.y, Sq2 = w4.x + w4.y;
            // one concurrent 2-wave butterfly for all 4 values
            Sk1 += __shfl_xor_sync(0xffffffffu, Sk1, 1);
            Sk2 += __shfl_xor_sync(0xffffffffu, Sk2, 1);
            Sq1 += __shfl_xor_sync(0xffffffffu, Sq1, 1);
            Sq2 += __shfl_xor_sync(0xffffffffu, Sq2, 1);
            Sk1 += __shfl_xor_sync(0xffffffffu, Sk1, 2);
            Sk2 += __shfl_xor_sync(0xffffffffu, Sk2, 2);
            Sq1 += __shfl_xor_sync(0xffffffffu, Sq1, 2);
            Sq2 += __shfl_xor_sync(0xffffffffu, Sq2, 2);

            // scalar chain
            const float c1 = b1v * fmaf(-a1v, Sk1, vv1);
            const float p2 = fmaf(a1v, Sk2, c1 * kk);
            const float c2 = b2v * fmaf(-a2v, p2, vv2);
            const float aa = a1v * a2v;
            const float ac = a2v * c1;
            const float o1 = fmaf(a1v, Sq1, c1 * kq11);
            const float o2 = fmaf(aa, Sq2, fmaf(ac, kq12, c2 * kq22));

            // 3-term S update: S = aa*S + ac*k1 + c2*k2  (k reloaded from smem)
            const ull aa2 = pack2(aa, aa);
            const ull ac2 = pack2(ac, ac);
            const ull c22 = pack2(c2, c2);
#pragma unroll
            for (int j = 0; j < 8; j++)
                S2[j] = ffma2(aa2, S2[j], ffma2(ac2, k1p[j], fmul2(c22, k2p[j])));

            if (kg == 0) {
                valout[vbase + (size_t)(c * CHUNK + s1) * Cq + vr] = fmaf(dp, vv1, o1);
                valout[vbase + (size_t)(c * CHUNK + s2) * Cq + vr] = fmaf(dp, vv2, o2);
            }
        }

        if (c + 2 < NCH) load_chunk(c + 2, stg);
        CP_COMMIT();
        CP_WAIT1();
        __syncwarp();
    }
}

// ---------------- epilogue: rmsnorm -> silu -> *gate -> fp16 -----------------
__global__ __launch_bounds__(256) void epi_kernel(
    const float* __restrict__ val, const float* __restrict__ gate,
    const float* __restrict__ onw, __half* __restrict__ ogh)
{
    const int gw = blockIdx.x * 8 + (threadIdx.x >> 5);
    const int lane = threadIdx.x & 31;
    const size_t off = (size_t)gw * 64 + lane * 2;
    float2 vl = *(const float2*)(val + off);
    float ss = vl.x * vl.x + vl.y * vl.y;
#pragma unroll
    for (int s = 16; s > 0; s >>= 1) ss += __shfl_xor_sync(0xffffffffu, ss, s);
    float r = rsqrtf(ss * (1.f / 64.f) + EPSq);
    float2 w2 = *(const float2*)(onw + lane * 2);
    float2 g2 = *(const float2*)(gate + off);
    float y0 = vl.x * r * w2.x;
    float y1 = vl.y * r * w2.y;
    float o0 = g2.x * (y0 / (1.f + expf(-y0)));
    float o1 = g2.y * (y1 / (1.f + expf(-y1)));
    *(u32*)(ogh + off) = packh(__float2half(o0), __float2half(o1));
}

// ---------------- launch ------------------------------------------------------
extern "C" void kernel_launch(void* const* d_in, const int* in_sizes, int n_in,
                              void* d_out, int out_size)
{
    const float* x    = (const float*)d_in[0];
    const float* Wq   = (const float*)d_in[1];
    const float* Wk   = (const float*)d_in[2];
    const float* Wv   = (const float*)d_in[3];
    const float* Wg   = (const float*)d_in[4];
    const float* Wo   = (const float*)d_in[5];
    const float* Wb   = (const float*)d_in[6];
    const float* bb   = (const float*)d_in[7];
    const float* Wgk  = (const float*)d_in[8];
    const float* bgk  = (const float*)d_in[9];
    const float* cqw  = (const float*)d_in[10];
    const float* cqb  = (const float*)d_in[11];
    const float* ckw  = (const float*)d_in[12];
    const float* ckb  = (const float*)d_in[13];
    const float* cvw  = (const float*)d_in[14];
    const float* cvb  = (const float*)d_in[15];
    const float* A_log = (const float*)d_in[16];
    const float* Dp   = (const float*)d_in[17];
    const float* dtb  = (const float*)d_in[18];
    const float* onw  = (const float*)d_in[19];
    float* out = (float*)d_out;

    float *qpre, *kpre, *vpre, *gbuf, *qn, *kn, *vn, *al, *be, *ct, *st;
    __half *xh, *wh, *ogh;
    cudaGetSymbolAddress((void**)&qpre, g_qpre);
    cudaGetSymbolAddress((void**)&kpre, g_kpre);
    cudaGetSymbolAddress((void**)&vpre, g_vpre);
    cudaGetSymbolAddress((void**)&gbuf, g_gate);
    cudaGetSymbolAddress((void**)&qn,   g_q);
    cudaGetSymbolAddress((void**)&kn,   g_k);
    cudaGetSymbolAddress((void**)&vn,   g_v);
    cudaGetSymbolAddress((void**)&al,   g_alT);
    cudaGetSymbolAddress((void**)&be,   g_beT);
    cudaGetSymbolAddress((void**)&ct,   g_cos);
    cudaGetSymbolAddress((void**)&st,   g_sin);
    cudaGetSymbolAddress((void**)&xh,   g_xh);
    cudaGetSymbolAddress((void**)&wh,   g_wh);
    cudaGetSymbolAddress((void**)&ogh,  g_ogh);

    cudaFuncSetAttribute(tgemm_nt,  cudaFuncAttributeMaxDynamicSharedMemorySize, TG_SMEM);
    cudaFuncSetAttribute(tgemm4_nt, cudaFuncAttributeMaxDynamicSharedMemorySize, TG_SMEM);

    prep_kernel<<<NB_PREP, 256>>>(x, Wq, Wk, Wv, Wg, Wo,
                                  Wb, bb, Wgk, bgk, A_log, dtb, be, al,
                                  ct, st, xh, wh);

    TG4Out outs = {qpre, kpre, vpre, gbuf};
    dim3 g4(Mq / 128, 32);
    tgemm4_nt<<<g4, 256, TG_SMEM>>>(xh, wh, outs, Cq, Cq);

    conv_rope_kernel<<<Bq * Hq * (Tq / 4), 256>>>(qpre, kpre, vpre,
                                                  cqw, cqb, ckw, ckb, cvw, cvb,
                                                  ct, st, qn, kn, vn);

    scan_kernel<<<Bq * Hq * NSEG, 32>>>(qn, kn, vn, al, be, Dp, qpre);

    epi_kernel<<<(Bq * Tq * Hq) / 8, 256>>>(qpre, gbuf, onw, ogh);

    const size_t CC = (size_t)Cq * Cq;
    dim3 gg(Mq / 128, Cq / 128);
    tgemm_nt<<<gg, 256, TG_SMEM>>>(ogh, wh + 4 * CC, out, Cq, Cq);
}

// round 14
// speedup vs baseline: 1.1447x; 1.1447x over previous
#include <cuda_runtime.h>
#include <cuda_bf16.h>
#include <cuda_fp16.h>
#include <math.h>

#define Bq 2
#define Tq 2048
#define Cq 1024
#define Hq 16
#define Dq 64
#define Mq (Bq*Tq)          // 4096
#define EPSq 1e-6f
#define CHUNK 16
#define NCH (Tq/CHUNK)      // 128
#define VSEG 8              // v-rows per scan warp
#define NSEG (Dq/VSEG)      // 8 -> 256 blocks

typedef unsigned long long ull;
typedef unsigned int u32;

// ---------------- packed f32x2 helpers ---------------------------------------
__device__ __forceinline__ ull ffma2(ull a, ull b, ull c) {
    ull d; asm("fma.rn.f32x2 %0, %1, %2, %3;" : "=l"(d) : "l"(a), "l"(b), "l"(c)); return d;
}
__device__ __forceinline__ ull fmul2(ull a, ull b) {
    ull d; asm("mul.rn.f32x2 %0, %1, %2;" : "=l"(d) : "l"(a), "l"(b)); return d;
}
__device__ __forceinline__ ull fadd2(ull a, ull b) {
    ull d; asm("add.rn.f32x2 %0, %1, %2;" : "=l"(d) : "l"(a), "l"(b)); return d;
}
__device__ __forceinline__ ull pack2(float x, float y) {
    ull d; asm("mov.b64 %0, {%1, %2};" : "=l"(d) : "f"(x), "f"(y)); return d;
}
__device__ __forceinline__ float2 unpack2(ull v) {
    float x, y; asm("mov.b64 {%0, %1}, %2;" : "=f"(x), "=f"(y) : "l"(v));
    return make_float2(x, y);
}
__device__ __forceinline__ void cpa16(void* s, const void* g) {
    asm volatile("cp.async.cg.shared.global [%0], [%1], 16;"
        :: "r"((unsigned)__cvta_generic_to_shared(s)), "l"(g));
}
#define CP_COMMIT() asm volatile("cp.async.commit_group;")
#define CP_WAIT1()  asm volatile("cp.async.wait_group 1;")

// ---------------- mma.sync helpers (fp16, f32 accum) --------------------------
__device__ __forceinline__ void ldsm4(u32* r, u32 addr) {
    asm volatile("ldmatrix.sync.aligned.m8n8.x4.shared.b16 {%0,%1,%2,%3}, [%4];"
        : "=r"(r[0]), "=r"(r[1]), "=r"(r[2]), "=r"(r[3]) : "r"(addr));
}
__device__ __forceinline__ void mma16816h(float* d, const u32* a, u32 b0, u32 b1) {
    asm volatile("mma.sync.aligned.m16n8k16.row.col.f32.f16.f16.f32 "
        "{%0,%1,%2,%3}, {%4,%5,%6,%7}, {%8,%9}, {%0,%1,%2,%3};"
        : "+f"(d[0]), "+f"(d[1]), "+f"(d[2]), "+f"(d[3])
        : "r"(a[0]), "r"(a[1]), "r"(a[2]), "r"(a[3]), "r"(b0), "r"(b1));
}

// ---------------- scratch ----------------------------------------------------
__device__ float g_qpre[(size_t)Mq*Cq];
__device__ float g_kpre[(size_t)Mq*Cq];
__device__ float g_vpre[(size_t)Mq*Cq];
__device__ float g_gate[(size_t)Mq*Cq];
__device__ float g_q[(size_t)Mq*Cq];
__device__ float g_k[(size_t)Mq*Cq];
__device__ float g_v[(size_t)Mq*Cq];
__device__ float g_alT[(size_t)Mq*Hq];
__device__ float g_beT[(size_t)Mq*Hq];
__device__ float g_cos[(size_t)Tq*32];
__device__ float g_sin[(size_t)Tq*32];
__device__ __half g_xh[(size_t)Mq*Cq];
__device__ __half g_wh[(size_t)5*Cq*Cq];
__device__ __half g_ogh[(size_t)Mq*Cq];

// ---------------- fp16 pack helpers ------------------------------------------
__device__ __forceinline__ u32 packh(__half a, __half b) {
    return (u32)__half_as_ushort(a) | ((u32)__half_as_ushort(b) << 16);
}

// ---------------- merged prep: bg + rope table + x->fp16 + weights->fp16 -----
#define BGM 8
#define NB_BG (Mq/BGM)                   // 512
#define NB_ROPE 256
#define NB_SPLITH (Mq*Cq/4/256)          // 4096
#define NB_WSPLIT (5*(Cq*Cq/4)/256)      // 5120
#define NB_PREP (NB_BG + NB_ROPE + NB_SPLITH + NB_WSPLIT)

__global__ __launch_bounds__(256) void prep_kernel(
    const float* __restrict__ x,
    const float* __restrict__ w0, const float* __restrict__ w1,
    const float* __restrict__ w2, const float* __restrict__ w3,
    const float* __restrict__ w4,
    const float* __restrict__ Wb, const float* __restrict__ bb,
    const float* __restrict__ Wgk, const float* __restrict__ bgk,
    const float* __restrict__ A_log, const float* __restrict__ dt_bias,
    float* __restrict__ beT, float* __restrict__ alT,
    float* __restrict__ ct, float* __restrict__ st,
    __half* __restrict__ xh, __half* __restrict__ whi)
{
    __shared__ __align__(16) float xs[BGM][Cq];
    int blk = blockIdx.x;

    if (blk < NB_BG) {
        const int m0 = blk * BGM;
        const int tid = threadIdx.x;
        for (int i = tid; i < BGM * Cq / 4; i += 256) {
            int r = i / (Cq / 4), cc = i % (Cq / 4);
            ((float4*)xs[r])[cc] = ((const float4*)(x + (size_t)(m0 + r) * Cq))[cc];
        }
        __syncthreads();

        const int warp = tid >> 5, lane = tid & 31;
#pragma unroll
        for (int nn = 0; nn < 4; nn++) {
            int n = warp * 4 + nn;
            const float* wr = (n < 16) ? (Wb + (size_t)n * Cq) : (Wgk + (size_t)(n - 16) * Cq);
            float wv[32];
#pragma unroll
            for (int j = 0; j < 32; j++) wv[j] = __ldg(wr + j * 32 + lane);
#pragma unroll
            for (int r = 0; r < BGM; r++) {
                float acc = 0.f;
#pragma unroll
                for (int j = 0; j < 32; j++) acc = fmaf(xs[r][j * 32 + lane], wv[j], acc);
#pragma unroll
                for (int s = 16; s > 0; s >>= 1) acc += __shfl_xor_sync(0xffffffffu, acc, s);
                if (lane == 0) {
                    int m = m0 + r;
                    int b = m >> 11, t = m & 2047;
                    if (n < 16) {
                        beT[((size_t)b * Hq + n) * Tq + t] = 1.f / (1.f + expf(-(acc + bb[n])));
                    } else {
                        int hh = n - 16;
                        float gv = acc + bgk[hh] + dt_bias[hh];
                        float sp = (gv > 20.f) ? gv : log1pf(expf(gv));
                        alT[((size_t)b * Hq + hh) * Tq + t] = expf(-expf(A_log[hh]) * sp);
                    }
                }
            }
        }
        return;
    }
    blk -= NB_BG;

    if (blk < NB_ROPE) {
        int idx = blk * 256 + threadIdx.x;
        int t = idx >> 5;
        int i = idx & 31;
        double ar = (double)i / 32.0;
        double scaled_base = 10000.0 * pow(32.0, 64.0 / 62.0);
        double inv_freq = pow(scaled_base, -ar);
        double wavelen = 2.0 * M_PI * pow(10000.0, ar);
        double mscale = (wavelen - 1.0) / 31.0;
        mscale = mscale < 0.0 ? 0.0 : (mscale > 1.0 ? 1.0 : mscale);
        double scale = 1.0 + 31.0 * mscale;
        float fr = (float)(((double)t / scale) * inv_freq);
        ct[idx] = cosf(fr);
        st[idx] = sinf(fr);
        return;
    }
    blk -= NB_ROPE;

    if (blk < NB_SPLITH) {
        int i = blk * 256 + threadIdx.x;
        float4 v = ((const float4*)x)[i];
        ((uint2*)xh)[i] = make_uint2(
            packh(__float2half(v.x), __float2half(v.y)),
            packh(__float2half(v.z), __float2half(v.w)));
        return;
    }
    blk -= NB_SPLITH;
    {
        const int R4 = (Cq * Cq) / 4;
        int i = blk * 256 + threadIdx.x;
        int r = i / R4;
        int li = i - r * R4;
        const float* src = (r == 0) ? w0 : (r == 1) ? w1 : (r == 2) ? w2
                          : (r == 3) ? w3 : w4;
        float4 v = ((const float4*)src)[li];
        ((uint2*)(whi + (size_t)r * Cq * Cq))[li] = make_uint2(
            packh(__float2half(v.x), __float2half(v.y)),
            packh(__float2half(v.z), __float2half(v.w)));
    }
}

// ---------------- tensor-core fp16 single-pass GEMM (NT), 2 CTAs/SM ----------
#define TILE_B 16384                  // 128 rows x 128 B
#define STG_B (2*TILE_B)              // Ah | Bh = 32KB per stage
#define NSTG 2
#define TG_SMEM (NSTG*STG_B)          // 64KB -> 2 CTAs per SM

__device__ __forceinline__ u32 swz_off(int row, int c) {
    return (u32)(row * 128 + (((u32)c ^ ((u32)row & 7) ^ (((u32)row >> 3) & 1)) << 4));
}

struct TG4Out { float *o0, *o1, *o2, *o3; };

__device__ __forceinline__ void tgemm_body(
    const __half* Ah, const __half* Bh,
    float* C, int K, int ldc, int m0, int n0, char* ts)
{
    const u32 sbase = (u32)__cvta_generic_to_shared(ts);
    const int tid = threadIdx.x;
    const int wid = tid >> 5;
    const int lane = tid & 31;
    const int warp_m = wid & 3;
    const int warp_n = wid >> 2;
    const int nchk = K / 64;

    const int lrow = tid >> 1;
    const int ch0 = (tid & 1) * 4;
    const char* gAh = (const char*)(Ah + (size_t)(m0 + lrow) * K) + ch0 * 16;
    const char* gBh = (const char*)(Bh + (size_t)(n0 + lrow) * K) + ch0 * 16;
    u32 soff[4];
#pragma unroll
    for (int i = 0; i < 4; i++) soff[i] = swz_off(lrow, ch0 + i);

    auto load_chunk = [&](int c, int stg) {
        const size_t go = (size_t)c * 128;
        char* base = ts + stg * STG_B;
#pragma unroll
        for (int i = 0; i < 4; i++) {
            cpa16(base + soff[i],          gAh + go + i * 16);
            cpa16(base + TILE_B + soff[i], gBh + go + i * 16);
        }
    };

    const int lq = lane >> 3;
    const int lr = lane & 7;
    const int rowA0 = warp_m * 32 + lr + (lq & 1) * 8;
    const int rowB0 = warp_n * 64 + lr + (lq & 1) * 8;
    const int cq = lq >> 1;

    float acc[2][8][4];
#pragma unroll
    for (int i = 0; i < 2; i++)
#pragma unroll
        for (int j = 0; j < 8; j++)
#pragma unroll
            for (int l = 0; l < 4; l++) acc[i][j][l] = 0.f;

    load_chunk(0, 0); CP_COMMIT();
    load_chunk(1, 1); CP_COMMIT();

    for (int c = 0; c < nchk; c++) {
        const int stg = c & 1;
        CP_WAIT1();
        __syncthreads();

        const u32 stb = sbase + stg * STG_B;
#pragma unroll
        for (int ks = 0; ks < 4; ks++) {
            const int cc = ks * 2 + cq;
            u32 ahf[2][4], bhf[4][4];
#pragma unroll
            for (int mt = 0; mt < 2; mt++)
                ldsm4(ahf[mt], stb + swz_off(rowA0 + mt * 16, cc));
#pragma unroll
            for (int ntp = 0; ntp < 4; ntp++)
                ldsm4(bhf[ntp], stb + TILE_B + swz_off(rowB0 + ntp * 16, cc));
#pragma unroll
            for (int mt = 0; mt < 2; mt++)
#pragma unroll
                for (int ntp = 0; ntp < 4; ntp++) {
                    mma16816h(acc[mt][ntp * 2],     ahf[mt], bhf[ntp][0], bhf[ntp][2]);
                    mma16816h(acc[mt][ntp * 2 + 1], ahf[mt], bhf[ntp][1], bhf[ntp][3]);
                }
        }

        __syncthreads();
        if (c + 2 < nchk) load_chunk(c + 2, stg);
        CP_COMMIT();
    }

    const int g = lane >> 2;
    const int tg = lane & 3;
#pragma unroll
    for (int mt = 0; mt < 2; mt++) {
        int mrow = m0 + warp_m * 32 + mt * 16 + g;
#pragma unroll
        for (int nt = 0; nt < 8; nt++) {
            int ncol = n0 + warp_n * 64 + nt * 8 + tg * 2;
            *(float2*)(C + (size_t)mrow * ldc + ncol) =
                make_float2(acc[mt][nt][0], acc[mt][nt][1]);
            *(float2*)(C + (size_t)(mrow + 8) * ldc + ncol) =
                make_float2(acc[mt][nt][2], acc[mt][nt][3]);
        }
    }
}

__global__ __launch_bounds__(256, 2) void tgemm_nt(
    const __half* __restrict__ Ah, const __half* __restrict__ Bh,
    float* __restrict__ C, int K, int ldc)
{
    extern __shared__ __align__(1024) char ts[];
    tgemm_body(Ah, Bh, C, K, ldc, blockIdx.x * 128, blockIdx.y * 128, ts);
}

__global__ __launch_bounds__(256, 2) void tgemm4_nt(
    const __half* __restrict__ Ah, const __half* __restrict__ Wh,
    TG4Out outs, int K, int ldc)
{
    extern __shared__ __align__(1024) char ts[];
    const int wsel = blockIdx.y >> 3;
    const int n0 = (blockIdx.y & 7) * 128;
    const size_t CC = (size_t)Cq * Cq;
    float* C = (wsel == 0) ? outs.o0 : (wsel == 1) ? outs.o1
             : (wsel == 2) ? outs.o2 : outs.o3;
    tgemm_body(Ah, Wh + wsel * CC, C, K, ldc, blockIdx.x * 128, n0, ts);
}

// ---------------- conv(K=4)+silu, RoPE + l2norm (4 t per block) --------------
__global__ __launch_bounds__(256) void conv_rope_kernel(
    const float* __restrict__ qpre, const float* __restrict__ kpre,
    const float* __restrict__ vpre,
    const float* __restrict__ cqw, const float* __restrict__ cqb,
    const float* __restrict__ ckw, const float* __restrict__ ckb,
    const float* __restrict__ cvw, const float* __restrict__ cvb,
    const float* __restrict__ ct, const float* __restrict__ st,
    float* __restrict__ qo, float* __restrict__ ko, float* __restrict__ vo)
{
    const int blk = blockIdx.x;
    const int b = blk / (Hq * (Tq / 4));
    const int rem = blk % (Hq * (Tq / 4));
    const int h = rem / (Tq / 4);
    const int t0 = (rem % (Tq / 4)) * 4;
    const int tid = threadIdx.x;

    __shared__ __align__(16) float spre[3][7][64];
    __shared__ float sq[4][64], sk[4][64];
    __shared__ float redq[4][2], redk[4][2];

    {
        const int NF4 = 3 * 7 * 16;
        for (int i = tid; i < NF4; i += 256) {
            int ten = i / 112;
            int r = (i % 112) / 16;
            int c4 = i % 16;
            int trow = t0 - 3 + r;
            float4 v = make_float4(0.f, 0.f, 0.f, 0.f);
            if (trow >= 0) {
                const float* src = (ten == 0) ? qpre : (ten == 1) ? kpre : vpre;
                v = ((const float4*)(src + ((size_t)b * Tq + trow) * Cq + h * 64))[c4];
            }
            ((float4*)&spre[ten][r][0])[c4] = v;
        }
    }
    __syncthreads();

    const int g = tid >> 6;
    const int d = tid & 63;
    const int t = t0 + g;
    const int c = h * Dq + d;
    const size_t gidx = ((size_t)b * Tq + t) * Cq + c;

    float aq = __ldg(cqb + c), ak = __ldg(ckb + c), av = __ldg(cvb + c);
#pragma unroll
    for (int i = 0; i < 4; i++) {
        float wq = __ldg(cqw + c * 4 + i);
        float wk = __ldg(ckw + c * 4 + i);
        float wv = __ldg(cvw + c * 4 + i);
        aq = fmaf(spre[0][g + i][d], wq, aq);
        ak = fmaf(spre[1][g + i][d], wk, ak);
        av = fmaf(spre[2][g + i][d], wv, av);
    }
    vo[gidx] = av / (1.f + expf(-av));
    sq[g][d] = aq / (1.f + expf(-aq));
    sk[g][d] = ak / (1.f + expf(-ak));
    __syncthreads();

    int j = d & 31;
    int ci = (2 * j) & 31;
    float ce = ct[(size_t)t * 32 + ci];
    float se = st[(size_t)t * 32 + ci];
    float q1 = sq[g][2 * j], q2 = sq[g][2 * j + 1];
    float k1 = sk[g][2 * j], k2 = sk[g][2 * j + 1];
    float rq = (d < 32) ? (q1 * ce - q2 * se) : (q1 * se + q2 * ce);
    float rk = (d < 32) ? (k1 * ce - k2 * se) : (k1 * se + k2 * ce);

    float sq2 = rq * rq, sk2 = rk * rk;
#pragma unroll
    for (int s = 16; s > 0; s >>= 1) {
        sq2 += __shfl_xor_sync(0xffffffffu, sq2, s);
        sk2 += __shfl_xor_sync(0xffffffffu, sk2, s);
    }
    int hw = (tid >> 5) & 1;
    if ((tid & 31) == 0) { redq[g][hw] = sq2; redk[g][hw] = sk2; }
    __syncthreads();
    float qn = redq[g][0] + redq[g][1];
    float kn = redk[g][0] + redk[g][1];
    float qinv = 1.f / fmaxf(sqrtf(qn), 1e-12f);
    float kinv = 1.f / fmaxf(sqrtf(kn), 1e-12f);
    qo[gidx] = rq * qinv;
    ko[gidx] = rk * kinv;
}

// ---------------- gated-delta scan (round-12 config + off-chain scalars) -----
__global__ __launch_bounds__(32, 8) void scan_kernel(
    const float* __restrict__ q, const float* __restrict__ k,
    const float* __restrict__ v,
    const float* __restrict__ alT, const float* __restrict__ beT,
    const float* __restrict__ Dp, float* __restrict__ valout)
{
    const int blk = blockIdx.x;
    const int bh = blk >> 3;
    const int seg = blk & 7;
    const int b = bh >> 4;
    const int h = bh & 15;
    const int lane = threadIdx.x;
    const int vr = lane >> 2;
    const int kg = lane & 3;

    __shared__ __align__(16) float sQ[2][CHUNK][64];
    __shared__ __align__(16) float sK[2][CHUNK][64];
    __shared__ __align__(16) float sV[2][CHUNK][VSEG];
    __shared__ __align__(16) float sA[2][CHUNK];
    __shared__ __align__(16) float sB[2][CHUNK];

    const size_t base  = (size_t)b * Tq * Cq + h * Dq;
    const size_t vbase = base + seg * VSEG;
    const size_t abb   = (size_t)bh * Tq;

    auto load_chunk = [&](int c, int stg) {
        const size_t rowoff = (size_t)c * CHUNK * Cq;
#pragma unroll
        for (int it = 0; it < 8; it++) {
            int idx = it * 32 + lane;
            int row = idx >> 4;
            int col = (idx & 15) * 4;
            cpa16(&sQ[stg][row][col], q + base + rowoff + (size_t)row * Cq + col);
            cpa16(&sK[stg][row][col], k + base + rowoff + (size_t)row * Cq + col);
        }
        {
            int row = lane >> 1;
            int col = (lane & 1) * 4;
            cpa16(&sV[stg][row][col], v + vbase + rowoff + (size_t)row * Cq + col);
        }
        if (lane < 4)      cpa16(&sA[stg][lane * 4], alT + abb + c * CHUNK + lane * 4);
        else if (lane < 8) cpa16(&sB[stg][(lane - 4) * 4], beT + abb + c * CHUNK + (lane - 4) * 4);
    };

    ull S2[8];
#pragma unroll
    for (int j = 0; j < 8; j++) S2[j] = 0ULL;
    const float dp = Dp[h];

    load_chunk(0, 0); CP_COMMIT();
    load_chunk(1, 1); CP_COMMIT();
    CP_WAIT1();
    __syncwarp();

    for (int c = 0; c < NCH; c++) {
        const int stg = c & 1;
#pragma unroll 4
        for (int s = 0; s < CHUNK; s++) {
            // scalar loads + off-chain precompute: by the time p lands,
            // abt/btv/a2 are ready and coef is a single FFMA.
            const float a  = sA[stg][s];
            const float bt = sB[stg][s];
            const float vv = sV[stg][s][vr];
            const float abt = a * bt;
            const float btv = bt * vv;
            const ull a2 = pack2(a, a);

            ull k2[8], q2[8];
            {
                const longlong2* kp = (const longlong2*)&sK[stg][s][kg * 16];
                const longlong2* qp = (const longlong2*)&sQ[stg][s][kg * 16];
#pragma unroll
                for (int j = 0; j < 4; j++) {
                    longlong2 kv = kp[j], qv = qp[j];
                    k2[2 * j] = (ull)kv.x; k2[2 * j + 1] = (ull)kv.y;
                    q2[2 * j] = (ull)qv.x; q2[2 * j + 1] = (ull)qv.y;
                }
            }

            ull pA = 0ULL, pB = 0ULL;
#pragma unroll
            for (int j = 0; j < 4; j++) {
                pA = ffma2(S2[j], k2[j], pA);
                pB = ffma2(S2[j + 4], k2[j + 4], pB);
            }
            float2 pu = unpack2(fadd2(pA, pB));
            float p = pu.x + pu.y;
            p += __shfl_xor_sync(0xffffffffu, p, 1);
            p += __shfl_xor_sync(0xffffffffu, p, 2);

            const float coef = fmaf(-abt, p, btv);
            const ull c2 = pack2(coef, coef);

            ull oA = 0ULL, oB = 0ULL;
#pragma unroll
            for (int j = 0; j < 4; j++) {
                S2[j] = ffma2(a2, S2[j], fmul2(c2, k2[j]));
                oA = ffma2(S2[j], q2[j], oA);
                S2[j + 4] = ffma2(a2, S2[j + 4], fmul2(c2, k2[j + 4]));
                oB = ffma2(S2[j + 4], q2[j + 4], oB);
            }
            float2 ou = unpack2(fadd2(oA, oB));
            float o = ou.x + ou.y;
            o += __shfl_xor_sync(0xffffffffu, o, 1);
            o += __shfl_xor_sync(0xffffffffu, o, 2);

            if (kg == 0) {
                float val = fmaf(dp, vv, o);
                valout[vbase + (size_t)(c * CHUNK + s) * Cq + vr] = val;
            }
        }
        if (c + 2 < NCH) load_chunk(c + 2, stg);
        CP_COMMIT();
        CP_WAIT1();
        __syncwarp();
    }
}

// ---------------- epilogue: rmsnorm -> silu -> *gate -> fp16 -----------------
__global__ __launch_bounds__(256) void epi_kernel(
    const float* __restrict__ val, const float* __restrict__ gate,
    const float* __restrict__ onw, __half* __restrict__ ogh)
{
    const int gw = blockIdx.x * 8 + (threadIdx.x >> 5);
    const int lane = threadIdx.x & 31;
    const size_t off = (size_t)gw * 64 + lane * 2;
    float2 vl = *(const float2*)(val + off);
    float ss = vl.x * vl.x + vl.y * vl.y;
#pragma unroll
    for (int s = 16; s > 0; s >>= 1) ss += __shfl_xor_sync(0xffffffffu, ss, s);
    float r = rsqrtf(ss * (1.f / 64.f) + EPSq);
    float2 w2 = *(const float2*)(onw + lane * 2);
    float2 g2 = *(const float2*)(gate + off);
    float y0 = vl.x * r * w2.x;
    float y1 = vl.y * r * w2.y;
    float o0 = g2.x * (y0 / (1.f + expf(-y0)));
    float o1 = g2.y * (y1 / (1.f + expf(-y1)));
    *(u32*)(ogh + off) = packh(__float2half(o0), __float2half(o1));
}

// ---------------- launch ------------------------------------------------------
extern "C" void kernel_launch(void* const* d_in, const int* in_sizes, int n_in,
                              void* d_out, int out_size)
{
    const float* x    = (const float*)d_in[0];
    const float* Wq   = (const float*)d_in[1];
    const float* Wk   = (const float*)d_in[2];
    const float* Wv   = (const float*)d_in[3];
    const float* Wg   = (const float*)d_in[4];
    const float* Wo   = (const float*)d_in[5];
    const float* Wb   = (const float*)d_in[6];
    const float* bb   = (const float*)d_in[7];
    const float* Wgk  = (const float*)d_in[8];
    const float* bgk  = (const float*)d_in[9];
    const float* cqw  = (const float*)d_in[10];
    const float* cqb  = (const float*)d_in[11];
    const float* ckw  = (const float*)d_in[12];
    const float* ckb  = (const float*)d_in[13];
    const float* cvw  = (const float*)d_in[14];
    const float* cvb  = (const float*)d_in[15];
    const float* A_log = (const float*)d_in[16];
    const float* Dp   = (const float*)d_in[17];
    const float* dtb  = (const float*)d_in[18];
    const float* onw  = (const float*)d_in[19];
    float* out = (float*)d_out;

    float *qpre, *kpre, *vpre, *gbuf, *qn, *kn, *vn, *al, *be, *ct, *st;
    __half *xh, *wh, *ogh;
    cudaGetSymbolAddress((void**)&qpre, g_qpre);
    cudaGetSymbolAddress((void**)&kpre, g_kpre);
    cudaGetSymbolAddress((void**)&vpre, g_vpre);
    cudaGetSymbolAddress((void**)&gbuf, g_gate);
    cudaGetSymbolAddress((void**)&qn,   g_q);
    cudaGetSymbolAddress((void**)&kn,   g_k);
    cudaGetSymbolAddress((void**)&vn,   g_v);
    cudaGetSymbolAddress((void**)&al,   g_alT);
    cudaGetSymbolAddress((void**)&be,   g_beT);
    cudaGetSymbolAddress((void**)&ct,   g_cos);
    cudaGetSymbolAddress((void**)&st,   g_sin);
    cudaGetSymbolAddress((void**)&xh,   g_xh);
    cudaGetSymbolAddress((void**)&wh,   g_wh);
    cudaGetSymbolAddress((void**)&ogh,  g_ogh);

    cudaFuncSetAttribute(tgemm_nt,  cudaFuncAttributeMaxDynamicSharedMemorySize, TG_SMEM);
    cudaFuncSetAttribute(tgemm4_nt, cudaFuncAttributeMaxDynamicSharedMemorySize, TG_SMEM);

    prep_kernel<<<NB_PREP, 256>>>(x, Wq, Wk, Wv, Wg, Wo,
                                  Wb, bb, Wgk, bgk, A_log, dtb, be, al,
                                  ct, st, xh, wh);

    TG4Out outs = {qpre, kpre, vpre, gbuf};
    dim3 g4(Mq / 128, 32);
    tgemm4_nt<<<g4, 256, TG_SMEM>>>(xh, wh, outs, Cq, Cq);

    conv_rope_kernel<<<Bq * Hq * (Tq / 4), 256>>>(qpre, kpre, vpre,
                                                  cqw, cqb, ckw, ckb, cvw, cvb,
                                                  ct, st, qn, kn, vn);

    scan_kernel<<<Bq * Hq * NSEG, 32>>>(qn, kn, vn, al, be, Dp, qpre);

    epi_kernel<<<(Bq * Tq * Hq) / 8, 256>>>(qpre, gbuf, onw, ogh);

    const size_t CC = (size_t)Cq * Cq;
    dim3 gg(Mq / 128, Cq / 128);
    tgemm_nt<<<gg, 256, TG_SMEM>>>(ogh, wh + 4 * CC, out, Cq, Cq);
}